// round 17
// baseline (speedup 1.0000x reference)
#include <cuda_runtime.h>
#include <cuda_bf16.h>
#include <cstdint>

#define CCONST 7.1998226
#define THREADS 256
#define DEPTH 4
#define STAGE_BYTES 8192        // one N=2048 float row
#define SMEM_SZ (DEPTH * STAGE_BYTES)
#define MAXB 64

__device__ double g_sum[MAXB];
__device__ unsigned int g_done = 0;

__device__ __forceinline__ uint32_t smem_u32(const void* p) {
    uint32_t a;
    asm("{ .reg .u64 t; cvta.to.shared.u64 t, %1; cvt.u32.u64 %0, t; }" : "=r"(a) : "l"(p));
    return a;
}
__device__ __forceinline__ void cp16(uint32_t saddr, const float* g) {
    asm volatile("cp.async.cg.shared.global [%0], [%1], 16;" :: "r"(saddr), "l"(g) : "memory");
}
__device__ __forceinline__ void cp_commit() {
    asm volatile("cp.async.commit_group;" ::: "memory");
}
template <int Nrem>
__device__ __forceinline__ void cp_wait() {
    asm volatile("cp.async.wait_group %0;" :: "n"(Nrem) : "memory");
}

// paired reciprocal: qx/dx + qy/dy = (qx*dy + qy*dx)/(dx*dy) -> 1 MUFU / 2 elems
__device__ __forceinline__ float pairdiv(float qx, float qy, float dx, float dy) {
    return __fdividef(fmaf(qx, dy, qy * dx), dx * dy);
}
__device__ __forceinline__ float row_l(const float4& qa, const float4& qc,
                                       const float4& da, const float4& dc) {
    return pairdiv(qa.x, qa.y, da.x, da.y) + pairdiv(qa.z, qa.w, da.z, da.w)
         + pairdiv(qc.x, qc.y, dc.x, dc.y) + pairdiv(qc.z, qc.w, dc.z, dc.w);
}

// N == 2048 fast path: per-thread cp.async pipeline, 6 CTAs/SM
__global__ __launch_bounds__(THREADS, 6)
void coulomb_cpa(const float* __restrict__ dij,
                 const float* __restrict__ q,
                 float* __restrict__ out,
                 int N, int B, unsigned int totalBlocks) {
    extern __shared__ char smem[];
    const int b   = blockIdx.y;
    const int bid = blockIdx.x;
    const int bpb = gridDim.x;
    const int tid = threadIdx.x;
    const int half = N >> 1;

    const float* qb = q + (size_t)b * N;
    const float4 qa = __ldg((const float4*)qb + tid);
    const float4 qc = __ldg((const float4*)qb + (half >> 2) + tid);

    // even contiguous row span
    const int r0 = (int)(((long long)bid * N) / bpb);
    const int r1 = (int)(((long long)(bid + 1) * N) / bpb);
    const int R  = r1 - r0;

    const float* rowbase = dij + ((size_t)b * N + r0) * (size_t)N;

    // per-thread smem slots: stage s, slice A at t*16, slice B at 4096 + t*16
    const uint32_t sb = smem_u32(smem);
    const uint32_t slotA = sb + tid * 16;
    const uint32_t slotB = sb + 4096 + tid * 16;
    const float* gA = rowbase + tid * 4;          // cols [4t, 4t+4)
    const float* gB = rowbase + half + tid * 4;   // cols [N/2+4t, ...)

    // prologue: fill DEPTH stages
    int issued = 0;
    #pragma unroll
    for (int s = 0; s < DEPTH; s++) {
        if (issued < R) {
            cp16(slotA + s * STAGE_BYTES, gA + (size_t)issued * N);
            cp16(slotB + s * STAGE_BYTES, gB + (size_t)issued * N);
            cp_commit();
            issued++;
        }
    }

    double acc = 0.0;
    float accf = 0.0f;

    for (int k = 0; k < R; k++) {
        const int s = k & (DEPTH - 1);
        cp_wait<DEPTH - 1>();               // oldest group (stage s) complete

        float4 da = *(const float4*)(smem + s * STAGE_BYTES + tid * 16);
        float4 dc = *(const float4*)(smem + s * STAGE_BYTES + 4096 + tid * 16);

        accf = fmaf(__ldg(qb + r0 + k), row_l(qa, qc, da, dc), accf);

        if ((k & 7) == 7) { acc += (double)accf; accf = 0.0f; }

        if (issued < R) {                   // refill stage s (same slot, ≥500cyc away)
            cp16(slotA + s * STAGE_BYTES, gA + (size_t)issued * N);
            cp16(slotB + s * STAGE_BYTES, gB + (size_t)issued * N);
            issued++;
        }
        cp_commit();                        // keep group count aligned with stages
    }
    acc += (double)accf;
    cp_wait<0>();

    // block reduce (fp64)
    #pragma unroll
    for (int off = 16; off; off >>= 1)
        acc += __shfl_down_sync(0xffffffffu, acc, off);

    __shared__ double sm[THREADS / 32];
    __shared__ bool is_last;
    if ((tid & 31) == 0) sm[tid >> 5] = acc;
    __syncthreads();

    if (tid < 32) {
        double v = (tid < THREADS / 32) ? sm[tid] : 0.0;
        #pragma unroll
        for (int off = 4; off; off >>= 1)
            v += __shfl_down_sync(0xffffffffu, v, off);
        if (tid == 0) {
            atomicAdd(&g_sum[b], v);
            __threadfence();
            unsigned int ticket = atomicInc(&g_done, totalBlocks - 1);
            is_last = (ticket == totalBlocks - 1);
        }
    }
    __syncthreads();

    if (is_last && tid < B) {
        double total = atomicAdd(&g_sum[tid], 0.0);
        out[tid] = (float)(CCONST * total);
        g_sum[tid] = 0.0;
    }
}

// generic fallback (R16 structure)
__global__ __launch_bounds__(THREADS, 4)
void coulomb_pair(const float* __restrict__ dij, const float* __restrict__ q,
                  float* __restrict__ out, int N, int B, unsigned int totalBlocks) {
    const int b = blockIdx.y, bpb = gridDim.x, tid = threadIdx.x;
    const int Tb = N >> 3, n4 = N >> 2, half4 = N >> 3;
    const float* qb = q + (size_t)b * N;
    const float4 qa = __ldg((const float4*)qb + tid);
    const float4 qc = __ldg((const float4*)qb + half4 + tid);
    double acc = 0.0;
    for (int rg = blockIdx.x; rg < Tb; rg += bpb) {
        const int row0 = rg * 8;
        const float4* base4 = (const float4*)(dij + ((size_t)b * N + row0) * (size_t)N);
        float acc0 = 0.f;
        #pragma unroll
        for (int h = 0; h < 8; h++) {
            const float4* p = base4 + (size_t)h * n4;
            float4 da = __ldcs(p + tid), dc = __ldcs(p + half4 + tid);
            acc0 = fmaf(__ldg(qb + row0 + h), row_l(qa, qc, da, dc), acc0);
        }
        acc += (double)acc0;
    }
    #pragma unroll
    for (int off = 16; off; off >>= 1) acc += __shfl_down_sync(0xffffffffu, acc, off);
    __shared__ double sm2[8];
    __shared__ bool last2;
    if ((tid & 31) == 0) sm2[tid >> 5] = acc;
    __syncthreads();
    if (tid < 32) {
        double v = (tid < 8) ? sm2[tid] : 0.0;
        #pragma unroll
        for (int off = 4; off; off >>= 1) v += __shfl_down_sync(0xffffffffu, v, off);
        if (tid == 0) {
            atomicAdd(&g_sum[b], v);
            __threadfence();
            last2 = (atomicInc(&g_done, totalBlocks - 1) == totalBlocks - 1);
        }
    }
    __syncthreads();
    if (last2 && tid < B) {
        double total = atomicAdd(&g_sum[tid], 0.0);
        out[tid] = (float)(CCONST * total);
        g_sum[tid] = 0.0;
    }
}

extern "C" void kernel_launch(void* const* d_in, const int* in_sizes, int n_in,
                              void* d_out, int out_size) {
    int di = 0;
    for (int i = 1; i < n_in; i++)
        if (in_sizes[i] > in_sizes[di]) di = i;
    const float* dij = (const float*)d_in[di];

    const long long B = (out_size > 0) ? out_size : 16;
    int qi = (di == 0 && n_in > 1) ? 1 : 0;
    for (int i = 0; i < n_in; i++) {
        if (i == di) continue;
        long long nq = in_sizes[i];
        long long Nc = nq / B;
        if (Nc > 0 && B * Nc * Nc == (long long)in_sizes[di]) { qi = i; break; }
    }
    const float* q = (const float*)d_in[qi];
    const int N = (int)((long long)in_sizes[qi] / B);

    int sm_count = 148;
    cudaDeviceGetAttribute(&sm_count, cudaDevAttrMultiProcessorCount, 0);

    if (N == 2048) {
        static bool attr = false;
        if (!attr) {
            cudaFuncSetAttribute(coulomb_cpa,
                                 cudaFuncAttributeMaxDynamicSharedMemorySize, SMEM_SZ);
            attr = true;
        }
        int bpb = (sm_count * 6) / (int)B;              // 152*6/16 = 57
        if (bpb < 1) bpb = 1;
        if (bpb > N) bpb = N;
        const unsigned int totalBlocks = (unsigned int)(bpb * B);
        dim3 grid(bpb, (unsigned)B);
        coulomb_cpa<<<grid, THREADS, SMEM_SZ>>>(dij, q, (float*)d_out, N, (int)B, totalBlocks);
    } else {
        int bpb = (sm_count * 4) / (int)B;
        if (bpb < 1) bpb = 1;
        if (bpb > (N >> 3)) bpb = (N >> 3);
        const unsigned int totalBlocks = (unsigned int)(bpb * B);
        dim3 grid(bpb, (unsigned)B);
        coulomb_pair<<<grid, THREADS>>>(dij, q, (float*)d_out, N, (int)B, totalBlocks);
    }
}